// round 3
// baseline (speedup 1.0000x reference)
#include <cuda_runtime.h>
#include <math.h>

// ---------------- problem constants ----------------
#define NB      4096
#define LATENT  768
#define COND    512
#define HIDDEN  1024
#define OUTD    512
#define NE      8
#define GATE_H  512
#define INPUT   1280   // LATENT + COND
#define INTER   1792   // LATENT + HIDDEN
#define NEG_SLOPE 0.01f
#define LN_EPS  1e-5f

// ---------------- scratch (device globals; no allocation allowed) -------------
__device__ float g_zc[NB * INPUT];      // concat(z, c)
__device__ float g_g1[NB * GATE_H];     // gate hidden 1
__device__ float g_g2[NB * GATE_H];     // gate hidden 2
__device__ float g_coeff[NB * NE];      // softmax gate coefficients
__device__ float g_x[NB * INTER];       // layernorm output (width 1280 or 1792)
__device__ float g_h[NB * HIDDEN];      // running layer_out

// ---------------- concat(z, c) -> zc ----------------
__global__ void concat_zc_kernel(const float* __restrict__ Z,
                                 const float* __restrict__ C,
                                 float* __restrict__ ZC) {
    int idx = blockIdx.x * blockDim.x + threadIdx.x;   // one float4 per thread
    const int total = NB * INPUT / 4;
    if (idx >= total) return;
    int row  = idx / (INPUT / 4);
    int col4 = idx - row * (INPUT / 4);
    float4 v;
    if (col4 < LATENT / 4)
        v = ((const float4*)Z)[row * (LATENT / 4) + col4];
    else
        v = ((const float4*)C)[row * (COND / 4) + (col4 - LATENT / 4)];
    ((float4*)ZC)[idx] = v;
}

// ---------------- generic SGEMM: C = leaky(A[M,K] @ W[K,N] + bias[N]) ----------
// BM=BN=128, BK=16, 256 threads, 8x8 microtile. M%128==0, N%128==0, K%16==0.
__global__ __launch_bounds__(256, 2)
void sgemm_bias_leaky(const float* __restrict__ A, const float* __restrict__ W,
                      const float* __restrict__ bias, float* __restrict__ C,
                      int K, int N) {
    __shared__ float As[16][132];
    __shared__ float Bs[16][128];
    const int tid  = threadIdx.x;
    const int row0 = blockIdx.y * 128;
    const int col0 = blockIdx.x * 128;
    const int tx   = tid & 15, ty = tid >> 4;
    const int a_m0 = tid >> 2;             // 0..63
    const int a_k0 = (tid & 3) * 4;        // 0,4,8,12
    const int a_m1 = a_m0 + 64;
    const int b_k0 = tid >> 5;             // 0..7
    const int b_n0 = (tid * 4) & 127;

    float acc[8][8];
#pragma unroll
    for (int i = 0; i < 8; i++)
#pragma unroll
        for (int j = 0; j < 8; j++) acc[i][j] = 0.f;

    const float* ar0 = A + (size_t)(row0 + a_m0) * K + a_k0;
    const float* ar1 = A + (size_t)(row0 + a_m1) * K + a_k0;
    const float* wp  = W + (size_t)b_k0 * N + col0 + b_n0;

    for (int k0 = 0; k0 < K; k0 += 16) {
        float4 av0 = *(const float4*)(ar0 + k0);
        float4 av1 = *(const float4*)(ar1 + k0);
        As[a_k0 + 0][a_m0] = av0.x; As[a_k0 + 1][a_m0] = av0.y;
        As[a_k0 + 2][a_m0] = av0.z; As[a_k0 + 3][a_m0] = av0.w;
        As[a_k0 + 0][a_m1] = av1.x; As[a_k0 + 1][a_m1] = av1.y;
        As[a_k0 + 2][a_m1] = av1.z; As[a_k0 + 3][a_m1] = av1.w;
        *(float4*)&Bs[b_k0][b_n0]     = *(const float4*)(wp);
        *(float4*)&Bs[b_k0 + 8][b_n0] = *(const float4*)(wp + (size_t)8 * N);
        wp += (size_t)16 * N;
        __syncthreads();
#pragma unroll
        for (int k = 0; k < 16; k++) {
            float a[8], b[8];
            float4 t;
            t = *(float4*)&As[k][ty * 8];     a[0]=t.x; a[1]=t.y; a[2]=t.z; a[3]=t.w;
            t = *(float4*)&As[k][ty * 8 + 4]; a[4]=t.x; a[5]=t.y; a[6]=t.z; a[7]=t.w;
            t = *(float4*)&Bs[k][tx * 8];     b[0]=t.x; b[1]=t.y; b[2]=t.z; b[3]=t.w;
            t = *(float4*)&Bs[k][tx * 8 + 4]; b[4]=t.x; b[5]=t.y; b[6]=t.z; b[7]=t.w;
#pragma unroll
            for (int i = 0; i < 8; i++)
#pragma unroll
                for (int j = 0; j < 8; j++)
                    acc[i][j] = fmaf(a[i], b[j], acc[i][j]);
        }
        __syncthreads();
    }

#pragma unroll
    for (int i = 0; i < 8; i++) {
        int row = row0 + ty * 8 + i;
#pragma unroll
        for (int j = 0; j < 8; j++) {
            int col = col0 + tx * 8 + j;
            float v = acc[i][j] + bias[col];
            v = v > 0.f ? v : NEG_SLOPE * v;
            C[(size_t)row * N + col] = v;
        }
    }
}

// ---------------- last gate layer + softmax ----------------
// coeff[b,:] = softmax(g2[b,:] @ W2[512,8] + b2)
__global__ void gate2_softmax_kernel(const float* __restrict__ G2,
                                     const float* __restrict__ W2,
                                     const float* __restrict__ b2,
                                     float* __restrict__ coeff) {
    __shared__ float sW[NE * GATE_H];   // transposed: sW[e*512 + i]
    const int tid = threadIdx.x;
    for (int idx = tid; idx < GATE_H * NE; idx += blockDim.x) {
        int i = idx >> 3, e = idx & 7;
        sW[e * GATE_H + i] = W2[idx];
    }
    __syncthreads();
    const int warp = tid >> 5, lane = tid & 31;
    const int row = blockIdx.x * 8 + warp;
    const float* xr = G2 + (size_t)row * GATE_H;
    float s[NE];
#pragma unroll
    for (int e = 0; e < NE; e++) s[e] = 0.f;
    for (int i = lane; i < GATE_H; i += 32) {
        float xv = xr[i];
#pragma unroll
        for (int e = 0; e < NE; e++) s[e] = fmaf(xv, sW[e * GATE_H + i], s[e]);
    }
#pragma unroll
    for (int e = 0; e < NE; e++) {
#pragma unroll
        for (int o = 16; o > 0; o >>= 1)
            s[e] += __shfl_xor_sync(0xffffffffu, s[e], o);
        s[e] += b2[e];
    }
    if (lane == 0) {
        float m = s[0];
#pragma unroll
        for (int e = 1; e < NE; e++) m = fmaxf(m, s[e]);
        float ex[NE], zsum = 0.f;
#pragma unroll
        for (int e = 0; e < NE; e++) { ex[e] = expf(s[e] - m); zsum += ex[e]; }
        float inv = 1.f / zsum;
#pragma unroll
        for (int e = 0; e < NE; e++) coeff[row * NE + e] = ex[e] * inv;
    }
}

// ---------------- LayerNorm over concat(z_row[768], s2_row[w2]) ----------------
__global__ void ln_concat_kernel(const float* __restrict__ Z,
                                 const float* __restrict__ S2, int w2,
                                 const float* __restrict__ gamma,
                                 const float* __restrict__ beta,
                                 float* __restrict__ Xout) {
    const int row = blockIdx.x;
    const int tid = threadIdx.x;   // 256 threads
    const int D = LATENT + w2;
    const float* a = Z + (size_t)row * LATENT;
    const float* b = S2 + (size_t)row * w2;

    float s = 0.f, ss = 0.f;
    for (int i = tid; i < LATENT; i += 256) { float v = a[i]; s += v; ss = fmaf(v, v, ss); }
    for (int i = tid; i < w2;     i += 256) { float v = b[i]; s += v; ss = fmaf(v, v, ss); }

    __shared__ float redS[8], redQ[8];
    __shared__ float sh_mu, sh_rstd;
#pragma unroll
    for (int o = 16; o > 0; o >>= 1) {
        s  += __shfl_xor_sync(0xffffffffu, s, o);
        ss += __shfl_xor_sync(0xffffffffu, ss, o);
    }
    int warp = tid >> 5, lane = tid & 31;
    if (lane == 0) { redS[warp] = s; redQ[warp] = ss; }
    __syncthreads();
    if (tid == 0) {
        float S = 0.f, Q = 0.f;
#pragma unroll
        for (int i = 0; i < 8; i++) { S += redS[i]; Q += redQ[i]; }
        float mu = S / (float)D;
        float var = Q / (float)D - mu * mu;
        sh_mu = mu;
        sh_rstd = rsqrtf(var + LN_EPS);
    }
    __syncthreads();
    const float mu = sh_mu, rstd = sh_rstd;
    float* xo = Xout + (size_t)row * D;
    for (int i = tid; i < LATENT; i += 256)
        xo[i] = (a[i] - mu) * rstd * gamma[i] + beta[i];
    for (int i = tid; i < w2; i += 256)
        xo[LATENT + i] = (b[i] - mu) * rstd * gamma[LATENT + i] + beta[LATENT + i];
}

// ---------------- soft-mixed expert GEMM (flattened over experts) --------------
// pre[b,n] = sum_{e,j} coeff[b,e]*X[b,j]*Wt[e*J+j, n]  + sum_e coeff[b,e]*bias[e,n]
// mode 0: out = leaky(pre); mode 1: out = leaky(prev + pre); mode 2: out = pre
__global__ __launch_bounds__(256, 2)
void mix_gemm(const float* __restrict__ X, int J,
              const float* __restrict__ Wt, const float* __restrict__ bias,
              const float* __restrict__ coeff,
              const float* __restrict__ prev, float* __restrict__ Cout,
              int N, int mode) {
    __shared__ float As[16][132];
    __shared__ float Bs[16][128];
    const int tid  = threadIdx.x;
    const int row0 = blockIdx.y * 128;
    const int col0 = blockIdx.x * 128;
    const int tx   = tid & 15, ty = tid >> 4;
    const int a_m0 = tid >> 2;
    const int a_k0 = (tid & 3) * 4;
    const int a_m1 = a_m0 + 64;
    const int b_k0 = tid >> 5;
    const int b_n0 = (tid * 4) & 127;

    float acc[8][8];
#pragma unroll
    for (int i = 0; i < 8; i++)
#pragma unroll
        for (int j = 0; j < 8; j++) acc[i][j] = 0.f;

    const float* xr0 = X + (size_t)(row0 + a_m0) * J + a_k0;
    const float* xr1 = X + (size_t)(row0 + a_m1) * J + a_k0;
    const float* wp  = Wt + (size_t)b_k0 * N + col0 + b_n0;

    for (int e = 0; e < NE; e++) {
        const float c0 = __ldg(&coeff[(row0 + a_m0) * NE + e]);
        const float c1 = __ldg(&coeff[(row0 + a_m1) * NE + e]);
        for (int j0 = 0; j0 < J; j0 += 16) {
            float4 av0 = *(const float4*)(xr0 + j0);
            float4 av1 = *(const float4*)(xr1 + j0);
            av0.x *= c0; av0.y *= c0; av0.z *= c0; av0.w *= c0;
            av1.x *= c1; av1.y *= c1; av1.z *= c1; av1.w *= c1;
            As[a_k0 + 0][a_m0] = av0.x; As[a_k0 + 1][a_m0] = av0.y;
            As[a_k0 + 2][a_m0] = av0.z; As[a_k0 + 3][a_m0] = av0.w;
            As[a_k0 + 0][a_m1] = av1.x; As[a_k0 + 1][a_m1] = av1.y;
            As[a_k0 + 2][a_m1] = av1.z; As[a_k0 + 3][a_m1] = av1.w;
            *(float4*)&Bs[b_k0][b_n0]     = *(const float4*)(wp);
            *(float4*)&Bs[b_k0 + 8][b_n0] = *(const float4*)(wp + (size_t)8 * N);
            wp += (size_t)16 * N;
            __syncthreads();
#pragma unroll
            for (int k = 0; k < 16; k++) {
                float a[8], b[8];
                float4 t;
                t = *(float4*)&As[k][ty * 8];     a[0]=t.x; a[1]=t.y; a[2]=t.z; a[3]=t.w;
                t = *(float4*)&As[k][ty * 8 + 4]; a[4]=t.x; a[5]=t.y; a[6]=t.z; a[7]=t.w;
                t = *(float4*)&Bs[k][tx * 8];     b[0]=t.x; b[1]=t.y; b[2]=t.z; b[3]=t.w;
                t = *(float4*)&Bs[k][tx * 8 + 4]; b[4]=t.x; b[5]=t.y; b[6]=t.z; b[7]=t.w;
#pragma unroll
                for (int i = 0; i < 8; i++)
#pragma unroll
                    for (int j = 0; j < 8; j++)
                        acc[i][j] = fmaf(a[i], b[j], acc[i][j]);
            }
            __syncthreads();
        }
    }

#pragma unroll
    for (int i = 0; i < 8; i++) {
        int row = row0 + ty * 8 + i;
        float c8[NE];
#pragma unroll
        for (int e = 0; e < NE; e++) c8[e] = coeff[row * NE + e];
#pragma unroll
        for (int j = 0; j < 8; j++) {
            int col = col0 + tx * 8 + j;
            float v = acc[i][j];
#pragma unroll
            for (int e = 0; e < NE; e++)
                v = fmaf(c8[e], bias[e * N + col], v);
            if (mode == 0) {
                v = v > 0.f ? v : NEG_SLOPE * v;
            } else if (mode == 1) {
                v += prev[(size_t)row * N + col];
                v = v > 0.f ? v : NEG_SLOPE * v;
            }
            Cout[(size_t)row * N + col] = v;
        }
    }
}

// ---------------- launch ----------------
extern "C" void kernel_launch(void* const* d_in, const int* in_sizes, int n_in,
                              void* d_out, int out_size) {
    const float* z = (const float*)d_in[0];
    const float* c = (const float*)d_in[1];
    const float *w[5], *bb[5], *lng[5], *lnb[5];

    // Disambiguate input ordering: setup_inputs dict order interleaves
    // (w_i, b_i, ln_g_i, ln_b_i); the reference signature groups all w/b first.
    // In dict order d_in[4] is ln_g0 (1280 elems); in signature order it's w1.
    if (in_sizes[4] == INPUT) {
        for (int i = 0; i < 5; i++) {
            w[i]   = (const float*)d_in[2 + 4 * i];
            bb[i]  = (const float*)d_in[3 + 4 * i];
            lng[i] = (const float*)d_in[4 + 4 * i];
            lnb[i] = (const float*)d_in[5 + 4 * i];
        }
    } else {
        for (int i = 0; i < 5; i++) {
            w[i]  = (const float*)d_in[2 + 2 * i];
            bb[i] = (const float*)d_in[3 + 2 * i];
        }
        for (int i = 0; i < 5; i++) {
            lng[i] = (const float*)d_in[12 + 2 * i];
            lnb[i] = (const float*)d_in[13 + 2 * i];
        }
    }
    const float* gW0 = (const float*)d_in[22];
    const float* gb0 = (const float*)d_in[23];
    const float* gW1 = (const float*)d_in[24];
    const float* gb1 = (const float*)d_in[25];
    const float* gW2 = (const float*)d_in[26];
    const float* gb2 = (const float*)d_in[27];
    float* out = (float*)d_out;

    float *zc, *g1, *g2, *coeff, *x, *h;
    cudaGetSymbolAddress((void**)&zc,    g_zc);
    cudaGetSymbolAddress((void**)&g1,    g_g1);
    cudaGetSymbolAddress((void**)&g2,    g_g2);
    cudaGetSymbolAddress((void**)&coeff, g_coeff);
    cudaGetSymbolAddress((void**)&x,     g_x);
    cudaGetSymbolAddress((void**)&h,     g_h);

    // 1) concat
    concat_zc_kernel<<<(NB * INPUT / 4 + 255) / 256, 256>>>(z, c, zc);

    // 2) gate MLP
    sgemm_bias_leaky<<<dim3(GATE_H / 128, NB / 128), 256>>>(zc, gW0, gb0, g1, INPUT, GATE_H);
    sgemm_bias_leaky<<<dim3(GATE_H / 128, NB / 128), 256>>>(g1, gW1, gb1, g2, GATE_H, GATE_H);
    gate2_softmax_kernel<<<NB / 8, 256>>>(g2, gW2, gb2, coeff);

    // 3) layer 0
    ln_concat_kernel<<<NB, 256>>>(z, c, COND, lng[0], lnb[0], x);
    mix_gemm<<<dim3(HIDDEN / 128, NB / 128), 256>>>(x, INPUT, w[0], bb[0], coeff,
                                                    nullptr, h, HIDDEN, 0);
    // 4) layers 1..3 (residual)
    for (int l = 1; l <= 3; l++) {
        ln_concat_kernel<<<NB, 256>>>(z, h, HIDDEN, lng[l], lnb[l], x);
        mix_gemm<<<dim3(HIDDEN / 128, NB / 128), 256>>>(x, INTER, w[l], bb[l], coeff,
                                                        h, h, HIDDEN, 1);
    }
    // 5) final layer (no residual / activation)
    ln_concat_kernel<<<NB, 256>>>(z, h, HIDDEN, lng[4], lnb[4], x);
    mix_gemm<<<dim3(OUTD / 128, NB / 128), 256>>>(x, INTER, w[4], bb[4], coeff,
                                                  nullptr, out, OUTD, 2);
}